// round 15
// baseline (speedup 1.0000x reference)
#include <cuda_runtime.h>
#include <cuda_fp16.h>
#include <cstdint>

// Dendrite: out[b,d] = sum_{v=1..255} lin_w[v-1] * prod_{s: bit(7-s) of v} p_s + lin_b
// v = hi*16+lo. inner[o][hi] = sum_lo Plo[o][lo]*W[hi][lo] via tensor cores
// (A = Plo 32x16 f16, B = W^T 16x16 f16, mma.m16n8k16, f32 accum).
// T=2 batch rows per warp: two fully independent compute streams live at once
// (8 independent MMAs, interleaved staging + epilogues) to cover latency.
// Epilogue: lane (r,m) owns output row r+8m; quad-transpose of C packets
// (16 shfl.xor per row) then local fp32 Phi weighting.

static constexpr int B = 8192;
static constexpr int D = 32;
static constexpr int S = 8;

__device__ __forceinline__ float fast_sigmoid_prehalved(float ah) {
    float t;
    asm("tanh.approx.f32 %0, %1;" : "=f"(t) : "f"(ah));
    return fmaf(0.5f, t, 0.5f);
}

__device__ __forceinline__ void mma16816(float c[4],
                                         uint32_t a0, uint32_t a1,
                                         uint32_t a2, uint32_t a3,
                                         uint32_t b0, uint32_t b1) {
    asm volatile(
        "mma.sync.aligned.m16n8k16.row.col.f32.f16.f16.f32 "
        "{%0,%1,%2,%3}, {%4,%5,%6,%7}, {%8,%9}, {%0,%1,%2,%3};"
        : "+f"(c[0]), "+f"(c[1]), "+f"(c[2]), "+f"(c[3])
        : "r"(a0), "r"(a1), "r"(a2), "r"(a3), "r"(b0), "r"(b1));
}

__device__ __forceinline__ uint32_t sw(uint32_t byte_off) {
    return byte_off ^ ((byte_off >> 3) & 0x70);
}

// 4x4 transpose across a quad (lanes share r, m = lane&3): new v[j] = old
// v[m] of quad-lane j (verified R14).
__device__ __forceinline__ void quad_transpose(float v[4], int m) {
    float x0 = (m & 2) ? v[0] : v[2];
    float r0 = __shfl_xor_sync(0xffffffffu, x0, 2);
    if (m & 2) v[0] = r0; else v[2] = r0;
    float x1 = (m & 2) ? v[1] : v[3];
    float r1 = __shfl_xor_sync(0xffffffffu, x1, 2);
    if (m & 2) v[1] = r1; else v[3] = r1;
    float y0 = (m & 1) ? v[0] : v[1];
    float s0 = __shfl_xor_sync(0xffffffffu, y0, 1);
    if (m & 1) v[0] = s0; else v[1] = s0;
    float y1 = (m & 1) ? v[2] : v[3];
    float s1 = __shfl_xor_sync(0xffffffffu, y1, 1);
    if (m & 1) v[2] = s1; else v[3] = s1;
}

__global__ __launch_bounds__(128)
void dendrite_kernel(const float* __restrict__ x,      // [B, 1, S]
                     const float* __restrict__ k,      // [D, S]
                     const float* __restrict__ w,      // [D, S]
                     const float* __restrict__ q,      // [D, S]
                     const float* __restrict__ lin_w,  // [1, 255]
                     const float* __restrict__ lin_b,  // [1]
                     float* __restrict__ out)          // [B, 1, D] -> b*D + d
{
    __shared__ __align__(16) char sWb[512];        // swizzled W half2 table
    __shared__ __align__(16) float4 sAhi[32];      // A[d][4..7],  A = 0.5*k*w
    __shared__ __align__(16) float4 sChi[32];      // C[d][4..7],  C = -0.5*k*q
    __shared__ __align__(16) float4 sAloP[32];     // A[row(l)][0..3], permuted
    __shared__ __align__(16) float4 sCloP[32];     // C[row(l)][0..3], permuted
    __shared__ __align__(16) char sAbuf[4][2048];  // per-warp A staging (2 rows)

    const int tid = threadIdx.x;              // 128 threads
    const int lane = tid & 31;
    const int warp = tid >> 5;                // 4 warps/block, 2 batch rows each
    const int b0 = (blockIdx.x * 4 + warp) * 2;

    // x rows b0, b0+1 (uniform across warp -> broadcast LDG.128)
    const float4* xp = reinterpret_cast<const float4*>(x + b0 * S);
    const float4 xa0 = xp[0], xb0 = xp[1];
    const float4 xa1 = xp[2], xb1 = xp[3];
    const float xs[2][8] = {
        {xa0.x, xa0.y, xa0.z, xa0.w, xb0.x, xb0.y, xb0.z, xb0.w},
        {xa1.x, xa1.y, xa1.z, xa1.w, xb1.x, xb1.y, xb1.z, xb1.w}};
    const float bias = lin_b[0];

    {
        // W table as half2 pairs along lo: h2 #i = (c[2i], c[2i+1]), c[0]=0
        const float cE = (tid == 0) ? 0.0f : lin_w[2 * tid - 1];
        const float cO = lin_w[2 * tid];
        const __half2 h = __floats2half2_rn(cE, cO);
        *reinterpret_cast<uint32_t*>(sWb + sw(tid * 4)) =
            *reinterpret_cast<const uint32_t*>(&h);

        // param tables: part 0: Ahi, 1: Chi, 2: AloP, 3: CloP
        const int dd = tid & 31;
        const int part = tid >> 5;
        const int s0 = (part < 2) ? 4 : 0;
        const float4 k4 = *reinterpret_cast<const float4*>(k + dd * 8 + s0);
        const float4 w4 = *reinterpret_cast<const float4*>(w + dd * 8 + s0);
        const float4 q4 = *reinterpret_cast<const float4*>(q + dd * 8 + s0);
        float4 Av, Cv;
        Av.x = 0.5f * k4.x * w4.x;  Cv.x = -0.5f * k4.x * q4.x;
        Av.y = 0.5f * k4.y * w4.y;  Cv.y = -0.5f * k4.y * q4.y;
        Av.z = 0.5f * k4.z * w4.z;  Cv.z = -0.5f * k4.z * q4.z;
        Av.w = 0.5f * k4.w * w4.w;  Cv.w = -0.5f * k4.w * q4.w;
        const int pos = 4 * (dd & 7) + (dd >> 3);  // row(pos) == dd
        if (part == 0)      sAhi[dd] = Av;
        else if (part == 1) sChi[dd] = Cv;
        else if (part == 2) sAloP[pos] = Av;
        else                sCloP[pos] = Cv;
    }
    __syncthreads();

    const int r = lane >> 2;                  // fragment row group 0..7
    const int m = lane & 3;                   // fragment col group 0..3

    // B fragments (shared by both rows): B[k=lo][n=hi] = W[hi][lo]
    const uint32_t b0_lo = *reinterpret_cast<const uint32_t*>(sWb + sw((r * 8 + m) * 4));
    const uint32_t b0_hi = *reinterpret_cast<const uint32_t*>(sWb + sw((r * 8 + m + 4) * 4));
    const uint32_t b1_lo = *reinterpret_cast<const uint32_t*>(sWb + sw(((r + 8) * 8 + m) * 4));
    const uint32_t b1_hi = *reinterpret_cast<const uint32_t*>(sWb + sw(((r + 8) * 8 + m + 4) * 4));

    // Param loads once, shared by both rows
    const float4 Ah = sAhi[lane], Ch = sChi[lane];
    const float4 Al = sAloP[lane], Cl = sCloP[lane];

    // Stage A (Plo rows, f16) for both batch rows; outer gates per row.
    float P0[2], P1[2], P2[2], P3[2];
#pragma unroll
    for (int rr = 0; rr < 2; ++rr) {
        const float p4f = fast_sigmoid_prehalved(fmaf(Ah.x, xs[rr][4], Ch.x));
        const float p5f = fast_sigmoid_prehalved(fmaf(Ah.y, xs[rr][5], Ch.y));
        const float p6f = fast_sigmoid_prehalved(fmaf(Ah.z, xs[rr][6], Ch.z));
        const float p7f = fast_sigmoid_prehalved(fmaf(Ah.w, xs[rr][7], Ch.w));
        float E[8];
        E[0] = 1.0f;       E[1] = p6f;
        E[2] = p5f;        E[3] = p5f * p6f;
        E[4] = p4f;        E[5] = p4f * p6f;
        E[6] = p4f * p5f;  E[7] = E[3] * p4f;
        uint32_t pk[8];
#pragma unroll
        for (int j = 0; j < 8; ++j) {
            const __half2 h = __floats2half2_rn(E[j], E[j] * p7f);
            pk[j] = *reinterpret_cast<const uint32_t*>(&h);
        }
        char* abase = sAbuf[warp] + rr * 1024;
        const uint32_t off = lane * 32;
        *reinterpret_cast<uint4*>(abase + sw(off))      = {pk[0], pk[1], pk[2], pk[3]};
        *reinterpret_cast<uint4*>(abase + sw(off + 16)) = {pk[4], pk[5], pk[6], pk[7]};

        // outer gates for this lane's output row = r + 8m
        P0[rr] = fast_sigmoid_prehalved(fmaf(Al.x, xs[rr][0], Cl.x));
        P1[rr] = fast_sigmoid_prehalved(fmaf(Al.y, xs[rr][1], Cl.y));
        P2[rr] = fast_sigmoid_prehalved(fmaf(Al.z, xs[rr][2], Cl.z));
        P3[rr] = fast_sigmoid_prehalved(fmaf(Al.w, xs[rr][3], Cl.w));
    }
    __syncwarp();

    // A fragments + 8 independent MMAs (both rows live -> ILP)
    float c00[2][4], c01[2][4], c10[2][4], c11[2][4];
#pragma unroll
    for (int rr = 0; rr < 2; ++rr) {
        const char* abase = sAbuf[warp] + rr * 1024;
#define LDA(row, j) (*reinterpret_cast<const uint32_t*>(abase + sw((row) * 32 + (j) * 4)))
        const uint32_t a0_0 = LDA(r, m),          a0_1 = LDA(r + 8, m);
        const uint32_t a0_2 = LDA(r, m + 4),      a0_3 = LDA(r + 8, m + 4);
        const uint32_t a1_0 = LDA(r + 16, m),     a1_1 = LDA(r + 24, m);
        const uint32_t a1_2 = LDA(r + 16, m + 4), a1_3 = LDA(r + 24, m + 4);
#undef LDA
#pragma unroll
        for (int j = 0; j < 4; ++j) {
            c00[rr][j] = 0.f; c01[rr][j] = 0.f; c10[rr][j] = 0.f; c11[rr][j] = 0.f;
        }
        mma16816(c00[rr], a0_0, a0_1, a0_2, a0_3, b0_lo, b0_hi);  // rows 0-15,  hi 0-7
        mma16816(c01[rr], a0_0, a0_1, a0_2, a0_3, b1_lo, b1_hi);  // rows 0-15,  hi 8-15
        mma16816(c10[rr], a1_0, a1_1, a1_2, a1_3, b0_lo, b0_hi);  // rows 16-31, hi 0-7
        mma16816(c11[rr], a1_0, a1_1, a1_2, a1_3, b1_lo, b1_hi);  // rows 16-31, hi 8-15
    }

    // Epilogue per row: quad transpose + local Phi weighting (verified R14).
#pragma unroll
    for (int rr = 0; rr < 2; ++rr) {
        float v0[4] = {c00[rr][0], c00[rr][2], c10[rr][0], c10[rr][2]};
        float v1[4] = {c00[rr][1], c00[rr][3], c10[rr][1], c10[rr][3]};
        float v2[4] = {c01[rr][0], c01[rr][2], c11[rr][0], c11[rr][2]};
        float v3[4] = {c01[rr][1], c01[rr][3], c11[rr][1], c11[rr][3]};
        quad_transpose(v0, m);
        quad_transpose(v1, m);
        quad_transpose(v2, m);
        quad_transpose(v3, m);

        float inn[4];
#pragma unroll
        for (int j = 0; j < 4; ++j) {
            const float tA = fmaf(P3[rr], v1[j], v0[j]);
            const float tB = fmaf(P3[rr], v3[j], v2[j]);
            inn[j] = fmaf(P0[rr], tB, tA);
        }
        const float g12 = P1[rr] * P2[rr];
        float res = fmaf(P2[rr], inn[1], inn[0]);
        res = fmaf(P1[rr], inn[2], res);
        res = fmaf(g12, inn[3], res);

        out[(b0 + rr) * D + (r + 8 * m)] = res + bias;
    }
}

extern "C" void kernel_launch(void* const* d_in, const int* in_sizes, int n_in,
                              void* d_out, int out_size) {
    const float* x     = (const float*)d_in[0];
    const float* k     = (const float*)d_in[1];
    const float* w     = (const float*)d_in[2];
    const float* q     = (const float*)d_in[3];
    // d_in[4] = mask (unused: fixed binary-expansion generation rule)
    const float* lin_w = (const float*)d_in[5];
    const float* lin_b = (const float*)d_in[6];
    float* out = (float*)d_out;

    // 128 threads = 4 warps; 2 batch rows per warp -> 8 rows/block -> 1024 blocks
    dendrite_kernel<<<B / 8, 128>>>(x, k, w, q, lin_w, lin_b, out);
}